// round 1
// baseline (speedup 1.0000x reference)
#include <cuda_runtime.h>
#include <cstdint>

#define N_ENT 50000
#define R_REL 16
#define D_EMB 64
#define F_IN  128
#define E_EDGE 100000
#define NL 2

// Scratch (device globals; allocation-free rule)
__device__ float g_emb[(size_t)N_ENT * D_EMB];                 // 12.8 MB
__device__ float g_acc[(size_t)N_ENT * D_EMB];                 // 12.8 MB
__device__ float g_Y[(size_t)R_REL * N_ENT * D_EMB];           // 204.8 MB

// ---------------------------------------------------------------------------
// Input GEMM: g_emb[n,d] = sum_k x[n,k] * ent_emb[k,d]   (K=128)
// Block: 256 threads, 64 rows x 64 cols tile; thread tile 4x4 (interleaved by 16)
// ---------------------------------------------------------------------------
#define KS_IN 132   // 128 + 4 pad (quad stride 33, odd -> conflict-free)

__global__ void k_input_gemm(const float* __restrict__ x,
                             const float* __restrict__ ent_emb,
                             int nrows) {
    extern __shared__ float smem[];
    float* sA  = smem;                 // [64][KS_IN]
    float* sBt = smem + 64 * KS_IN;    // [64][KS_IN]  (Bt[d][k] = ent_emb[k][d])

    const int tid  = threadIdx.x;
    const int base = blockIdx.x * 64;

    // load Bt (transpose ent_emb [128,64] -> [64][128])
    for (int idx = tid; idx < F_IN * D_EMB; idx += 256) {
        int k = idx / D_EMB, d = idx % D_EMB;
        sBt[d * KS_IN + k] = ent_emb[idx];
    }
    // load A tile (float4)
    for (int idx4 = tid; idx4 < 64 * (F_IN / 4); idx4 += 256) {
        int row = idx4 / (F_IN / 4), kq = idx4 % (F_IN / 4);
        float4 v = make_float4(0.f, 0.f, 0.f, 0.f);
        if (base + row < nrows)
            v = reinterpret_cast<const float4*>(x + (size_t)(base + row) * F_IN)[kq];
        *reinterpret_cast<float4*>(&sA[row * KS_IN + kq * 4]) = v;
    }
    __syncthreads();

    const int cs = tid & 15;
    const int rs = tid >> 4;
    float acc[4][4];
#pragma unroll
    for (int i = 0; i < 4; i++)
#pragma unroll
        for (int j = 0; j < 4; j++) acc[i][j] = 0.f;

#pragma unroll 8
    for (int kq = 0; kq < F_IN / 4; kq++) {
        float4 a[4], b[4];
#pragma unroll
        for (int i = 0; i < 4; i++)
            a[i] = *reinterpret_cast<const float4*>(&sA[(rs + 16 * i) * KS_IN + kq * 4]);
#pragma unroll
        for (int j = 0; j < 4; j++)
            b[j] = *reinterpret_cast<const float4*>(&sBt[(cs + 16 * j) * KS_IN + kq * 4]);
#pragma unroll
        for (int i = 0; i < 4; i++)
#pragma unroll
            for (int j = 0; j < 4; j++)
                acc[i][j] += a[i].x * b[j].x + a[i].y * b[j].y +
                             a[i].z * b[j].z + a[i].w * b[j].w;
    }

#pragma unroll
    for (int i = 0; i < 4; i++) {
        int row = base + rs + 16 * i;
        if (row < nrows) {
#pragma unroll
            for (int j = 0; j < 4; j++)
                g_emb[(size_t)row * D_EMB + cs + 16 * j] = acc[i][j];
        }
    }
}

// ---------------------------------------------------------------------------
// Transform: for relation r = blockIdx.y:
//   g_Y[r][n][d] = sum_e g_emb[n][e] * W[r][d][e]     (K=64)
// ---------------------------------------------------------------------------
#define KS_T 68     // 64 + 4 pad (quad stride 17, odd)

__global__ void k_transform(const float* __restrict__ Wl /* [16][64][64] */,
                            int nrows) {
    __shared__ float sA[64 * KS_T];
    __shared__ float sBt[64 * KS_T];

    const int tid  = threadIdx.x;
    const int base = blockIdx.x * 64;
    const int r    = blockIdx.y;
    const float* W = Wl + (size_t)r * D_EMB * D_EMB;   // [d][e]
    float* C       = g_Y + (size_t)r * N_ENT * D_EMB;

    // W is already [d][e] row-major: copy straight in (float4)
    for (int idx4 = tid; idx4 < D_EMB * (D_EMB / 4); idx4 += 256) {
        int d = idx4 / (D_EMB / 4), kq = idx4 % (D_EMB / 4);
        *reinterpret_cast<float4*>(&sBt[d * KS_T + kq * 4]) =
            reinterpret_cast<const float4*>(W + (size_t)d * D_EMB)[kq];
    }
    for (int idx4 = tid; idx4 < 64 * (D_EMB / 4); idx4 += 256) {
        int row = idx4 / (D_EMB / 4), kq = idx4 % (D_EMB / 4);
        float4 v = make_float4(0.f, 0.f, 0.f, 0.f);
        if (base + row < nrows)
            v = reinterpret_cast<const float4*>(g_emb + (size_t)(base + row) * D_EMB)[kq];
        *reinterpret_cast<float4*>(&sA[row * KS_T + kq * 4]) = v;
    }
    __syncthreads();

    const int cs = tid & 15;
    const int rs = tid >> 4;
    float acc[4][4];
#pragma unroll
    for (int i = 0; i < 4; i++)
#pragma unroll
        for (int j = 0; j < 4; j++) acc[i][j] = 0.f;

#pragma unroll
    for (int kq = 0; kq < D_EMB / 4; kq++) {
        float4 a[4], b[4];
#pragma unroll
        for (int i = 0; i < 4; i++)
            a[i] = *reinterpret_cast<const float4*>(&sA[(rs + 16 * i) * KS_T + kq * 4]);
#pragma unroll
        for (int j = 0; j < 4; j++)
            b[j] = *reinterpret_cast<const float4*>(&sBt[(cs + 16 * j) * KS_T + kq * 4]);
#pragma unroll
        for (int i = 0; i < 4; i++)
#pragma unroll
            for (int j = 0; j < 4; j++)
                acc[i][j] += a[i].x * b[j].x + a[i].y * b[j].y +
                             a[i].z * b[j].z + a[i].w * b[j].w;
    }

#pragma unroll
    for (int i = 0; i < 4; i++) {
        int row = base + rs + 16 * i;
        if (row < nrows) {
#pragma unroll
            for (int j = 0; j < 4; j++)
                C[(size_t)row * D_EMB + cs + 16 * j] = acc[i][j];
        }
    }
}

// ---------------------------------------------------------------------------
// Zero accumulator
// ---------------------------------------------------------------------------
__global__ void k_zero_acc() {
    int i = blockIdx.x * blockDim.x + threadIdx.x;
    if (i < N_ENT * D_EMB / 4)
        reinterpret_cast<float4*>(g_acc)[i] = make_float4(0.f, 0.f, 0.f, 0.f);
}

// ---------------------------------------------------------------------------
// Edge scatter: acc[row] += val * Y[r][col]
// 16 threads per edge (one float4 each), consecutive -> 256B coalesced
// ---------------------------------------------------------------------------
__global__ void k_scatter(const int* __restrict__ erow,
                          const int* __restrict__ ecol,
                          const float* __restrict__ eval) {
    long long t = (long long)blockIdx.x * blockDim.x + threadIdx.x;
    int seg = (int)(t >> 4);
    if (seg >= R_REL * E_EDGE) return;
    int d4 = (int)(t & 15);

    int row = __ldg(erow + seg);
    int col = __ldg(ecol + seg);
    float v = __ldg(eval + seg);
    int r   = seg / E_EDGE;

    float4 q = reinterpret_cast<const float4*>(
                   g_Y + ((size_t)r * N_ENT + col) * D_EMB)[d4];
    float* dst = g_acc + (size_t)row * D_EMB + d4 * 4;
    asm volatile("red.global.add.v4.f32 [%0], {%1,%2,%3,%4};"
                 :: "l"(dst), "f"(v * q.x), "f"(v * q.y),
                    "f"(v * q.z), "f"(v * q.w)
                 : "memory");
}

// ---------------------------------------------------------------------------
// ReLU: emb = max(acc, 0)
// ---------------------------------------------------------------------------
__global__ void k_relu() {
    int i = blockIdx.x * blockDim.x + threadIdx.x;
    if (i < N_ENT * D_EMB / 4) {
        float4 v = reinterpret_cast<const float4*>(g_acc)[i];
        v.x = fmaxf(v.x, 0.f); v.y = fmaxf(v.y, 0.f);
        v.z = fmaxf(v.z, 0.f); v.w = fmaxf(v.w, 0.f);
        reinterpret_cast<float4*>(g_emb)[i] = v;
    }
}

// ---------------------------------------------------------------------------
// L2 normalize rows: out[n] = emb[n] / max(||emb[n]||, 1e-12)
// one warp per row; each lane holds 2 elements
// ---------------------------------------------------------------------------
__global__ void k_normalize(float* __restrict__ out) {
    int row  = blockIdx.x * 8 + (threadIdx.x >> 5);
    int lane = threadIdx.x & 31;
    if (row >= N_ENT) return;
    const float* e = g_emb + (size_t)row * D_EMB;
    float v0 = e[lane], v1 = e[lane + 32];
    float ss = v0 * v0 + v1 * v1;
#pragma unroll
    for (int o = 16; o > 0; o >>= 1) ss += __shfl_xor_sync(0xFFFFFFFFu, ss, o);
    float s = 1.0f / fmaxf(sqrtf(ss), 1e-12f);
    out[(size_t)row * D_EMB + lane]      = v0 * s;
    out[(size_t)row * D_EMB + lane + 32] = v1 * s;
}

// ---------------------------------------------------------------------------
extern "C" void kernel_launch(void* const* d_in, const int* in_sizes, int n_in,
                              void* d_out, int out_size) {
    const float* x         = (const float*)d_in[0];   // [N, 128]
    const float* ent_emb   = (const float*)d_in[1];   // [128, 64]
    const float* rel_trans = (const float*)d_in[2];   // [2, 16, 64, 64]
    const int*   erow      = (const int*)d_in[3];     // [16, 100000]
    const int*   ecol      = (const int*)d_in[4];     // [16, 100000]
    const float* eval      = (const float*)d_in[5];   // [16, 100000]
    float* out             = (float*)d_out;           // [N, 64]

    const int row_blocks = (N_ENT + 63) / 64;                 // 782
    const int elem_blocks = (N_ENT * D_EMB / 4 + 255) / 256;  // 3125
    const int scatter_blocks = (R_REL * E_EDGE * 16) / 256;   // 100000

    const size_t smem_in = 2 * 64 * KS_IN * sizeof(float);    // ~68KB
    cudaFuncSetAttribute(k_input_gemm,
                         cudaFuncAttributeMaxDynamicSharedMemorySize,
                         (int)smem_in);

    k_input_gemm<<<row_blocks, 256, smem_in>>>(x, ent_emb, N_ENT);

    for (int l = 0; l < NL; l++) {
        const float* Wl = rel_trans + (size_t)l * R_REL * D_EMB * D_EMB;
        k_transform<<<dim3(row_blocks, R_REL), 256>>>(Wl, N_ENT);
        k_zero_acc<<<elem_blocks, 256>>>();
        k_scatter<<<scatter_blocks, 256>>>(erow, ecol, eval);
        k_relu<<<elem_blocks, 256>>>();
    }

    k_normalize<<<(N_ENT + 7) / 8, 256>>>(out);
}